// round 12
// baseline (speedup 1.0000x reference)
#include <cuda_runtime.h>

// LSTM featurizer: T=1024 steps, B=64, V=256, E=256, H=1024.
// Persistent kernel: 128 CTAs (one per SM), each CTA owns 8 hidden columns
// (=> 32 gate rows). W_hh slice (128KB) + Gx table (32KB) in SMEM.
// R12: 256 threads (2 warps/SMSP), thread tile 4 batch x 8 rows (64-reg acc,
// no spills), warps = 4 k-slices x 2 batch-halves (no duplicated h LDGs).

static constexpr int T_STEPS = 1024;
static constexpr int NB      = 64;
static constexpr int NV      = 256;
static constexpr int NE      = 256;
static constexpr int NH      = 1024;
static constexpr int NCTA    = 128;
static constexpr int NTHR    = 256;

typedef unsigned long long ull;

__device__ float    g_h[2][NB][NH];
__device__ unsigned g_epoch;
__device__ unsigned g_count;

__device__ __forceinline__ void fma2(ull& acc, ull a, ull b) {
    asm("fma.rn.f32x2 %0, %1, %2, %0;" : "+l"(acc) : "l"(a), "l"(b));
}
__device__ __forceinline__ float2 unpack2(ull v) {
    float2 r;
    asm("mov.b64 {%0, %1}, %2;" : "=f"(r.x), "=f"(r.y) : "l"(v));
    return r;
}
__device__ __forceinline__ float fast_sigmoid(float x) {
    return __fdividef(1.f, 1.f + __expf(-x));
}
__device__ __forceinline__ float fast_tanh(float x) {
    x = fmaxf(x, -44.f);
    float e = __expf(-2.f * x);
    return __fdividef(1.f - e, 1.f + e);
}

__device__ __forceinline__ void grid_barrier() {
    __syncthreads();
    if (threadIdx.x == 0) {
        unsigned e = *((volatile unsigned*)&g_epoch);
        unsigned a = atomicAdd(&g_count, 1);
        if (a == NCTA - 1) {
            *((volatile unsigned*)&g_count) = 0;
            __threadfence();
            atomicAdd(&g_epoch, 1);
        } else {
            while (*((volatile unsigned*)&g_epoch) == e) { __nanosleep(64); }
        }
    }
    __syncthreads();
}

// SMEM layout (floats)
static constexpr int W_S_FLOATS  = 32 * 1024 + 16;   // row r at r*1024 + (r>>3)*4
static constexpr int GX_FLOATS   = NV * 32;
static constexpr int PS_W        = 64 * 33;          // per-k-slice psum, b-stride 33
static constexpr int PSUM_FLOATS = 4 * PS_W;         // 8448 (also W_ih^T staging: 8192)
static constexpr int SMEM_FLOATS = W_S_FLOATS + GX_FLOATS + PSUM_FLOATS + 512 + 512 + 128;
static constexpr int SMEM_BYTES  = SMEM_FLOATS * 4;

__global__ void __launch_bounds__(NTHR, 1)
lstm_persistent(const int* __restrict__ tokens, const int* __restrict__ seq_len,
                const float* __restrict__ emb, const float* __restrict__ W_ih,
                const float* __restrict__ W_hh, const float* __restrict__ b_ih,
                const float* __restrict__ b_hh, float* __restrict__ out)
{
    extern __shared__ float smem[];
    float* W_s   = smem;
    float* Gx_s  = W_s  + W_S_FLOATS;
    float* psum  = Gx_s + GX_FLOATS;      // also W_ih^T staging in prologue
    float* c_s   = psum + PSUM_FLOATS;
    float* lc_s  = c_s  + 512;
    int*   tok_s = (int*)(lc_s + 512);
    int*   sl_s  = tok_s + 64;

    const int tid  = threadIdx.x;
    const int cta  = blockIdx.x;
    const int j0   = cta * 8;
    const int warp = tid >> 5;            // 0..7
    const int lane = tid & 31;
    const int kw   = warp & 3;            // k-slice (256 wide)
    const int bh   = warp >> 2;           // batch half (32 wide)

    // ---------------- prologue ----------------
    for (int idx = tid; idx < 32 * NH; idx += NTHR) {
        int r = idx >> 10, k = idx & 1023;
        int grow = (r >> 3) * NH + j0 + (r & 7);
        W_s[r * 1024 + (r >> 3) * 4 + k] = W_hh[grow * NH + k];
    }
    for (int idx = tid; idx < 32 * NE; idx += NTHR) {
        int r = idx >> 8, e = idx & 255;
        int grow = (r >> 3) * NH + j0 + (r & 7);
        psum[e * 32 + r] = W_ih[grow * NE + e];
    }
    for (int idx = tid; idx < NB * 8; idx += NTHR) {
        int b = idx >> 3, col = idx & 7;
        g_h[0][b][j0 + col] = 0.f;
        c_s[idx]  = 0.f;
        lc_s[idx] = 0.f;
    }
    if (tid < NB) sl_s[tid] = seq_len[tid];
    __syncthreads();

    // Gx[v][r] = b_ih+b_hh + emb[v] . W_ih[row(r)]
    {
        int grow   = (lane >> 3) * NH + j0 + (lane & 7);
        float bias = b_ih[grow] + b_hh[grow];
        for (int v = warp; v < NV; v += 8) {
            const float4* ev = (const float4*)(emb + v * NE);
            float s = 0.f;
            #pragma unroll 8
            for (int e4 = 0; e4 < NE / 4; ++e4) {
                float4 e = __ldg(ev + e4);
                int eb = e4 * 4;
                s += e.x * psum[(eb + 0) * 32 + lane];
                s += e.y * psum[(eb + 1) * 32 + lane];
                s += e.z * psum[(eb + 2) * 32 + lane];
                s += e.w * psum[(eb + 3) * 32 + lane];
            }
            Gx_s[v * 32 + lane] = s + bias;
        }
    }
    __threadfence();
    grid_barrier();

    // ---------------- main recurrence ----------------
    // thread tile: 4 batches x 8 gate rows. lane: bg=lane>>2 (batch subgroup),
    // rg=lane&3 (row group of 8). Warp: kw = k-slice of 256, bh = batch half.
    const int bg = lane >> 2;
    const int rg = lane & 3;
    const int kbase = kw * 256;
    const int b0 = bh * 32 + bg * 4;

    for (int t = 0; t < T_STEPS; ++t) {
        const float* hp = &g_h[t & 1][0][0];
        float*       hn = &g_h[(t + 1) & 1][0][0];
        if (tid < NB) tok_s[tid] = tokens[t * NB + tid];

        ull acc[4][8];
        #pragma unroll
        for (int i = 0; i < 4; ++i)
            #pragma unroll
            for (int j = 0; j < 8; ++j) acc[i][j] = 0ull;

        const float* hbase = hp  + b0 * NH + kbase;
        const float* wbase = W_s + (rg * 8) * 1024 + rg * 4 + kbase;

        longlong2 ha[4], hb[4];
        #pragma unroll
        for (int i = 0; i < 4; ++i)
            ha[i] = __ldcg((const longlong2*)(hbase + i * NH));

        #pragma unroll 1
        for (int k4 = 0; k4 < 64; k4 += 2) {
            #pragma unroll
            for (int i = 0; i < 4; ++i)
                hb[i] = __ldcg((const longlong2*)(hbase + i * NH + (k4 + 1) * 4));
            #pragma unroll
            for (int j = 0; j < 8; ++j) {
                longlong2 wv = *(const longlong2*)(wbase + j * 1024 + k4 * 4);
                #pragma unroll
                for (int i = 0; i < 4; ++i) {
                    fma2(acc[i][j], (ull)ha[i].x, (ull)wv.x);
                    fma2(acc[i][j], (ull)ha[i].y, (ull)wv.y);
                }
            }
            if (k4 + 2 < 64) {
                #pragma unroll
                for (int i = 0; i < 4; ++i)
                    ha[i] = __ldcg((const longlong2*)(hbase + i * NH + (k4 + 2) * 4));
            }
            #pragma unroll
            for (int j = 0; j < 8; ++j) {
                longlong2 wv = *(const longlong2*)(wbase + j * 1024 + (k4 + 1) * 4);
                #pragma unroll
                for (int i = 0; i < 4; ++i) {
                    fma2(acc[i][j], (ull)hb[i].x, (ull)wv.x);
                    fma2(acc[i][j], (ull)hb[i].y, (ull)wv.y);
                }
            }
        }

        // partial sums -> SMEM (b-stride 33 to avoid STS bank conflicts)
        #pragma unroll
        for (int i = 0; i < 4; ++i) {
            int b = b0 + i;
            #pragma unroll
            for (int j = 0; j < 8; ++j) {
                float2 f = unpack2(acc[i][j]);
                psum[kw * PS_W + b * 33 + rg * 8 + j] = f.x + f.y;
            }
        }
        __syncthreads();

        // reduce across 4 k-slice warps + gate nonlinearities; 2 (b,col)/thread
        #pragma unroll
        for (int q = 0; q < 2; ++q) {
            int idx = q * NTHR + tid;
            int b = idx >> 3, col = idx & 7;
            float gi = 0.f, gf = 0.f, gg = 0.f, go = 0.f;
            #pragma unroll
            for (int w = 0; w < 4; ++w) {
                const float* pp = psum + w * PS_W + b * 33 + col;
                gi += pp[0]; gf += pp[8]; gg += pp[16]; go += pp[24];
            }
            const float* gx = Gx_s + tok_s[b] * 32 + col;
            gi += gx[0]; gf += gx[8]; gg += gx[16]; go += gx[24];

            float c_old = c_s[idx];
            float cn = fast_sigmoid(gf) * c_old + fast_sigmoid(gi) * fast_tanh(gg);
            float hv = fast_sigmoid(go) * fast_tanh(cn);
            c_s[idx] = cn;
            if ((t == 0) || (t < sl_s[b])) lc_s[idx] = cn;
            hn[b * NH + j0 + col] = hv;
        }
        __threadfence();
        grid_barrier();
    }

    // ---------------- epilogue ----------------
    #pragma unroll
    for (int q = 0; q < 2; ++q) {
        int idx = q * NTHR + tid;
        int b = idx >> 3, col = idx & 7;
        out[b * NH + j0 + col] = lc_s[idx];
    }
}

extern "C" void kernel_launch(void* const* d_in, const int* in_sizes, int n_in,
                              void* d_out, int out_size)
{
    const int*   tokens = (const int*)d_in[0];
    const int*   seqlen = (const int*)d_in[1];
    const float* emb    = (const float*)d_in[2];
    const float* W_ih   = (const float*)d_in[3];
    const float* W_hh   = (const float*)d_in[4];
    const float* b_ih   = (const float*)d_in[5];
    const float* b_hh   = (const float*)d_in[6];
    float*       out    = (float*)d_out;

    cudaFuncSetAttribute(lstm_persistent,
                         cudaFuncAttributeMaxDynamicSharedMemorySize, SMEM_BYTES);
    lstm_persistent<<<NCTA, NTHR, SMEM_BYTES>>>(tokens, seqlen, emb, W_ih, W_hh,
                                                b_ih, b_hh, out);
}

// round 14
// speedup vs baseline: 1.0467x; 1.0467x over previous
#include <cuda_runtime.h>

// LSTM featurizer: T=1024 steps, B=64, V=256, E=256, H=1024.
// Persistent kernel: 128 CTAs (one per SM), each CTA owns 8 hidden columns
// (=> 32 gate rows). W_hh slice (128KB) + Gx table (32KB) in SMEM.
// R12: 256 threads (2 warps/SMSP), thread tile 4 batch x 8 rows (64-reg acc,
// no spills), warps = 4 k-slices x 2 batch-halves (no duplicated h LDGs).

static constexpr int T_STEPS = 1024;
static constexpr int NB      = 64;
static constexpr int NV      = 256;
static constexpr int NE      = 256;
static constexpr int NH      = 1024;
static constexpr int NCTA    = 128;
static constexpr int NTHR    = 256;

typedef unsigned long long ull;

__device__ float    g_h[2][NB][NH];
__device__ unsigned g_epoch;
__device__ unsigned g_count;

__device__ __forceinline__ void fma2(ull& acc, ull a, ull b) {
    asm("fma.rn.f32x2 %0, %1, %2, %0;" : "+l"(acc) : "l"(a), "l"(b));
}
__device__ __forceinline__ float2 unpack2(ull v) {
    float2 r;
    asm("mov.b64 {%0, %1}, %2;" : "=f"(r.x), "=f"(r.y) : "l"(v));
    return r;
}
__device__ __forceinline__ float fast_sigmoid(float x) {
    return __fdividef(1.f, 1.f + __expf(-x));
}
__device__ __forceinline__ float fast_tanh(float x) {
    x = fmaxf(x, -44.f);
    float e = __expf(-2.f * x);
    return __fdividef(1.f - e, 1.f + e);
}

__device__ __forceinline__ void grid_barrier() {
    __syncthreads();
    if (threadIdx.x == 0) {
        unsigned e = *((volatile unsigned*)&g_epoch);
        unsigned a = atomicAdd(&g_count, 1);
        if (a == NCTA - 1) {
            *((volatile unsigned*)&g_count) = 0;
            __threadfence();
            atomicAdd(&g_epoch, 1);
        } else {
            while (*((volatile unsigned*)&g_epoch) == e) { __nanosleep(64); }
        }
    }
    __syncthreads();
}

// SMEM layout (floats)
static constexpr int W_S_FLOATS  = 32 * 1024 + 16;   // row r at r*1024 + (r>>3)*4
static constexpr int GX_FLOATS   = NV * 32;
static constexpr int PS_W        = 64 * 33;          // per-k-slice psum, b-stride 33
static constexpr int PSUM_FLOATS = 4 * PS_W;         // 8448 (also W_ih^T staging: 8192)
static constexpr int SMEM_FLOATS = W_S_FLOATS + GX_FLOATS + PSUM_FLOATS + 512 + 512 + 128;
static constexpr int SMEM_BYTES  = SMEM_FLOATS * 4;

__global__ void __launch_bounds__(NTHR, 1)
lstm_persistent(const int* __restrict__ tokens, const int* __restrict__ seq_len,
                const float* __restrict__ emb, const float* __restrict__ W_ih,
                const float* __restrict__ W_hh, const float* __restrict__ b_ih,
                const float* __restrict__ b_hh, float* __restrict__ out)
{
    extern __shared__ float smem[];
    float* W_s   = smem;
    float* Gx_s  = W_s  + W_S_FLOATS;
    float* psum  = Gx_s + GX_FLOATS;      // also W_ih^T staging in prologue
    float* c_s   = psum + PSUM_FLOATS;
    float* lc_s  = c_s  + 512;
    int*   tok_s = (int*)(lc_s + 512);
    int*   sl_s  = tok_s + 64;

    const int tid  = threadIdx.x;
    const int cta  = blockIdx.x;
    const int j0   = cta * 8;
    const int warp = tid >> 5;            // 0..7
    const int lane = tid & 31;
    const int kw   = warp & 3;            // k-slice (256 wide)
    const int bh   = warp >> 2;           // batch half (32 wide)

    // ---------------- prologue ----------------
    for (int idx = tid; idx < 32 * NH; idx += NTHR) {
        int r = idx >> 10, k = idx & 1023;
        int grow = (r >> 3) * NH + j0 + (r & 7);
        W_s[r * 1024 + (r >> 3) * 4 + k] = W_hh[grow * NH + k];
    }
    for (int idx = tid; idx < 32 * NE; idx += NTHR) {
        int r = idx >> 8, e = idx & 255;
        int grow = (r >> 3) * NH + j0 + (r & 7);
        psum[e * 32 + r] = W_ih[grow * NE + e];
    }
    for (int idx = tid; idx < NB * 8; idx += NTHR) {
        int b = idx >> 3, col = idx & 7;
        g_h[0][b][j0 + col] = 0.f;
        c_s[idx]  = 0.f;
        lc_s[idx] = 0.f;
    }
    if (tid < NB) sl_s[tid] = seq_len[tid];
    __syncthreads();

    // Gx[v][r] = b_ih+b_hh + emb[v] . W_ih[row(r)]
    {
        int grow   = (lane >> 3) * NH + j0 + (lane & 7);
        float bias = b_ih[grow] + b_hh[grow];
        for (int v = warp; v < NV; v += 8) {
            const float4* ev = (const float4*)(emb + v * NE);
            float s = 0.f;
            #pragma unroll 8
            for (int e4 = 0; e4 < NE / 4; ++e4) {
                float4 e = __ldg(ev + e4);
                int eb = e4 * 4;
                s += e.x * psum[(eb + 0) * 32 + lane];
                s += e.y * psum[(eb + 1) * 32 + lane];
                s += e.z * psum[(eb + 2) * 32 + lane];
                s += e.w * psum[(eb + 3) * 32 + lane];
            }
            Gx_s[v * 32 + lane] = s + bias;
        }
    }
    __threadfence();
    grid_barrier();

    // ---------------- main recurrence ----------------
    // thread tile: 4 batches x 8 gate rows. lane: bg=lane>>2 (batch subgroup),
    // rg=lane&3 (row group of 8). Warp: kw = k-slice of 256, bh = batch half.
    const int bg = lane >> 2;
    const int rg = lane & 3;
    const int kbase = kw * 256;
    const int b0 = bh * 32 + bg * 4;

    for (int t = 0; t < T_STEPS; ++t) {
        const float* hp = &g_h[t & 1][0][0];
        float*       hn = &g_h[(t + 1) & 1][0][0];
        if (tid < NB) tok_s[tid] = tokens[t * NB + tid];

        ull acc[4][8];
        #pragma unroll
        for (int i = 0; i < 4; ++i)
            #pragma unroll
            for (int j = 0; j < 8; ++j) acc[i][j] = 0ull;

        const float* hbase = hp  + b0 * NH + kbase;
        const float* wbase = W_s + (rg * 8) * 1024 + rg * 4 + kbase;

        longlong2 ha[4], hb[4];
        #pragma unroll
        for (int i = 0; i < 4; ++i)
            ha[i] = __ldcg((const longlong2*)(hbase + i * NH));

        #pragma unroll 1
        for (int k4 = 0; k4 < 64; k4 += 2) {
            #pragma unroll
            for (int i = 0; i < 4; ++i)
                hb[i] = __ldcg((const longlong2*)(hbase + i * NH + (k4 + 1) * 4));
            #pragma unroll
            for (int j = 0; j < 8; ++j) {
                longlong2 wv = *(const longlong2*)(wbase + j * 1024 + k4 * 4);
                #pragma unroll
                for (int i = 0; i < 4; ++i) {
                    fma2(acc[i][j], (ull)ha[i].x, (ull)wv.x);
                    fma2(acc[i][j], (ull)ha[i].y, (ull)wv.y);
                }
            }
            if (k4 + 2 < 64) {
                #pragma unroll
                for (int i = 0; i < 4; ++i)
                    ha[i] = __ldcg((const longlong2*)(hbase + i * NH + (k4 + 2) * 4));
            }
            #pragma unroll
            for (int j = 0; j < 8; ++j) {
                longlong2 wv = *(const longlong2*)(wbase + j * 1024 + (k4 + 1) * 4);
                #pragma unroll
                for (int i = 0; i < 4; ++i) {
                    fma2(acc[i][j], (ull)hb[i].x, (ull)wv.x);
                    fma2(acc[i][j], (ull)hb[i].y, (ull)wv.y);
                }
            }
        }

        // partial sums -> SMEM (b-stride 33 to avoid STS bank conflicts)
        #pragma unroll
        for (int i = 0; i < 4; ++i) {
            int b = b0 + i;
            #pragma unroll
            for (int j = 0; j < 8; ++j) {
                float2 f = unpack2(acc[i][j]);
                psum[kw * PS_W + b * 33 + rg * 8 + j] = f.x + f.y;
            }
        }
        __syncthreads();

        // reduce across 4 k-slice warps + gate nonlinearities; 2 (b,col)/thread
        #pragma unroll
        for (int q = 0; q < 2; ++q) {
            int idx = q * NTHR + tid;
            int b = idx >> 3, col = idx & 7;
            float gi = 0.f, gf = 0.f, gg = 0.f, go = 0.f;
            #pragma unroll
            for (int w = 0; w < 4; ++w) {
                const float* pp = psum + w * PS_W + b * 33 + col;
                gi += pp[0]; gf += pp[8]; gg += pp[16]; go += pp[24];
            }
            const float* gx = Gx_s + tok_s[b] * 32 + col;
            gi += gx[0]; gf += gx[8]; gg += gx[16]; go += gx[24];

            float c_old = c_s[idx];
            float cn = fast_sigmoid(gf) * c_old + fast_sigmoid(gi) * fast_tanh(gg);
            float hv = fast_sigmoid(go) * fast_tanh(cn);
            c_s[idx] = cn;
            if ((t == 0) || (t < sl_s[b])) lc_s[idx] = cn;
            hn[b * NH + j0 + col] = hv;
        }
        __threadfence();
        grid_barrier();
    }

    // ---------------- epilogue ----------------
    #pragma unroll
    for (int q = 0; q < 2; ++q) {
        int idx = q * NTHR + tid;
        int b = idx >> 3, col = idx & 7;
        out[b * NH + j0 + col] = lc_s[idx];
    }
}

extern "C" void kernel_launch(void* const* d_in, const int* in_sizes, int n_in,
                              void* d_out, int out_size)
{
    const int*   tokens = (const int*)d_in[0];
    const int*   seqlen = (const int*)d_in[1];
    const float* emb    = (const float*)d_in[2];
    const float* W_ih   = (const float*)d_in[3];
    const float* W_hh   = (const float*)d_in[4];
    const float* b_ih   = (const float*)d_in[5];
    const float* b_hh   = (const float*)d_in[6];
    float*       out    = (float*)d_out;

    cudaFuncSetAttribute(lstm_persistent,
                         cudaFuncAttributeMaxDynamicSharedMemorySize, SMEM_BYTES);
    lstm_persistent<<<NCTA, NTHR, SMEM_BYTES>>>(tokens, seqlen, emb, W_ih, W_hh,
                                                b_ih, b_hh, out);
}

// round 17
// speedup vs baseline: 1.0502x; 1.0033x over previous
#include <cuda_runtime.h>

// LSTM featurizer: T=1024 steps, B=64, V=256, E=256, H=1024.
// Persistent kernel: 128 CTAs (one per SM), each CTA owns 8 hidden columns
// (=> 32 gate rows). W_hh slice (128KB) + Gx table (32KB) in SMEM.
// R12: 256 threads (2 warps/SMSP), thread tile 4 batch x 8 rows (64-reg acc,
// no spills), warps = 4 k-slices x 2 batch-halves (no duplicated h LDGs).

static constexpr int T_STEPS = 1024;
static constexpr int NB      = 64;
static constexpr int NV      = 256;
static constexpr int NE      = 256;
static constexpr int NH      = 1024;
static constexpr int NCTA    = 128;
static constexpr int NTHR    = 256;

typedef unsigned long long ull;

__device__ float    g_h[2][NB][NH];
__device__ unsigned g_epoch;
__device__ unsigned g_count;

__device__ __forceinline__ void fma2(ull& acc, ull a, ull b) {
    asm("fma.rn.f32x2 %0, %1, %2, %0;" : "+l"(acc) : "l"(a), "l"(b));
}
__device__ __forceinline__ float2 unpack2(ull v) {
    float2 r;
    asm("mov.b64 {%0, %1}, %2;" : "=f"(r.x), "=f"(r.y) : "l"(v));
    return r;
}
__device__ __forceinline__ float fast_sigmoid(float x) {
    return __fdividef(1.f, 1.f + __expf(-x));
}
__device__ __forceinline__ float fast_tanh(float x) {
    x = fmaxf(x, -44.f);
    float e = __expf(-2.f * x);
    return __fdividef(1.f - e, 1.f + e);
}

__device__ __forceinline__ void grid_barrier() {
    __syncthreads();
    if (threadIdx.x == 0) {
        unsigned e = *((volatile unsigned*)&g_epoch);
        unsigned a = atomicAdd(&g_count, 1);
        if (a == NCTA - 1) {
            *((volatile unsigned*)&g_count) = 0;
            __threadfence();
            atomicAdd(&g_epoch, 1);
        } else {
            while (*((volatile unsigned*)&g_epoch) == e) { __nanosleep(64); }
        }
    }
    __syncthreads();
}

// SMEM layout (floats)
static constexpr int W_S_FLOATS  = 32 * 1024 + 16;   // row r at r*1024 + (r>>3)*4
static constexpr int GX_FLOATS   = NV * 32;
static constexpr int PS_W        = 64 * 33;          // per-k-slice psum, b-stride 33
static constexpr int PSUM_FLOATS = 4 * PS_W;         // 8448 (also W_ih^T staging: 8192)
static constexpr int SMEM_FLOATS = W_S_FLOATS + GX_FLOATS + PSUM_FLOATS + 512 + 512 + 128;
static constexpr int SMEM_BYTES  = SMEM_FLOATS * 4;

__global__ void __launch_bounds__(NTHR, 1)
lstm_persistent(const int* __restrict__ tokens, const int* __restrict__ seq_len,
                const float* __restrict__ emb, const float* __restrict__ W_ih,
                const float* __restrict__ W_hh, const float* __restrict__ b_ih,
                const float* __restrict__ b_hh, float* __restrict__ out)
{
    extern __shared__ float smem[];
    float* W_s   = smem;
    float* Gx_s  = W_s  + W_S_FLOATS;
    float* psum  = Gx_s + GX_FLOATS;      // also W_ih^T staging in prologue
    float* c_s   = psum + PSUM_FLOATS;
    float* lc_s  = c_s  + 512;
    int*   tok_s = (int*)(lc_s + 512);
    int*   sl_s  = tok_s + 64;

    const int tid  = threadIdx.x;
    const int cta  = blockIdx.x;
    const int j0   = cta * 8;
    const int warp = tid >> 5;            // 0..7
    const int lane = tid & 31;
    const int kw   = warp & 3;            // k-slice (256 wide)
    const int bh   = warp >> 2;           // batch half (32 wide)

    // ---------------- prologue ----------------
    for (int idx = tid; idx < 32 * NH; idx += NTHR) {
        int r = idx >> 10, k = idx & 1023;
        int grow = (r >> 3) * NH + j0 + (r & 7);
        W_s[r * 1024 + (r >> 3) * 4 + k] = W_hh[grow * NH + k];
    }
    for (int idx = tid; idx < 32 * NE; idx += NTHR) {
        int r = idx >> 8, e = idx & 255;
        int grow = (r >> 3) * NH + j0 + (r & 7);
        psum[e * 32 + r] = W_ih[grow * NE + e];
    }
    for (int idx = tid; idx < NB * 8; idx += NTHR) {
        int b = idx >> 3, col = idx & 7;
        g_h[0][b][j0 + col] = 0.f;
        c_s[idx]  = 0.f;
        lc_s[idx] = 0.f;
    }
    if (tid < NB) sl_s[tid] = seq_len[tid];
    __syncthreads();

    // Gx[v][r] = b_ih+b_hh + emb[v] . W_ih[row(r)]
    {
        int grow   = (lane >> 3) * NH + j0 + (lane & 7);
        float bias = b_ih[grow] + b_hh[grow];
        for (int v = warp; v < NV; v += 8) {
            const float4* ev = (const float4*)(emb + v * NE);
            float s = 0.f;
            #pragma unroll 8
            for (int e4 = 0; e4 < NE / 4; ++e4) {
                float4 e = __ldg(ev + e4);
                int eb = e4 * 4;
                s += e.x * psum[(eb + 0) * 32 + lane];
                s += e.y * psum[(eb + 1) * 32 + lane];
                s += e.z * psum[(eb + 2) * 32 + lane];
                s += e.w * psum[(eb + 3) * 32 + lane];
            }
            Gx_s[v * 32 + lane] = s + bias;
        }
    }
    __threadfence();
    grid_barrier();

    // ---------------- main recurrence ----------------
    // thread tile: 4 batches x 8 gate rows. lane: bg=lane>>2 (batch subgroup),
    // rg=lane&3 (row group of 8). Warp: kw = k-slice of 256, bh = batch half.
    const int bg = lane >> 2;
    const int rg = lane & 3;
    const int kbase = kw * 256;
    const int b0 = bh * 32 + bg * 4;

    for (int t = 0; t < T_STEPS; ++t) {
        const float* hp = &g_h[t & 1][0][0];
        float*       hn = &g_h[(t + 1) & 1][0][0];
        if (tid < NB) tok_s[tid] = tokens[t * NB + tid];

        ull acc[4][8];
        #pragma unroll
        for (int i = 0; i < 4; ++i)
            #pragma unroll
            for (int j = 0; j < 8; ++j) acc[i][j] = 0ull;

        const float* hbase = hp  + b0 * NH + kbase;
        const float* wbase = W_s + (rg * 8) * 1024 + rg * 4 + kbase;

        longlong2 ha[4], hb[4];
        #pragma unroll
        for (int i = 0; i < 4; ++i)
            ha[i] = __ldcg((const longlong2*)(hbase + i * NH));

        #pragma unroll 1
        for (int k4 = 0; k4 < 64; k4 += 2) {
            #pragma unroll
            for (int i = 0; i < 4; ++i)
                hb[i] = __ldcg((const longlong2*)(hbase + i * NH + (k4 + 1) * 4));
            #pragma unroll
            for (int j = 0; j < 8; ++j) {
                longlong2 wv = *(const longlong2*)(wbase + j * 1024 + k4 * 4);
                #pragma unroll
                for (int i = 0; i < 4; ++i) {
                    fma2(acc[i][j], (ull)ha[i].x, (ull)wv.x);
                    fma2(acc[i][j], (ull)ha[i].y, (ull)wv.y);
                }
            }
            if (k4 + 2 < 64) {
                #pragma unroll
                for (int i = 0; i < 4; ++i)
                    ha[i] = __ldcg((const longlong2*)(hbase + i * NH + (k4 + 2) * 4));
            }
            #pragma unroll
            for (int j = 0; j < 8; ++j) {
                longlong2 wv = *(const longlong2*)(wbase + j * 1024 + (k4 + 1) * 4);
                #pragma unroll
                for (int i = 0; i < 4; ++i) {
                    fma2(acc[i][j], (ull)hb[i].x, (ull)wv.x);
                    fma2(acc[i][j], (ull)hb[i].y, (ull)wv.y);
                }
            }
        }

        // partial sums -> SMEM (b-stride 33 to avoid STS bank conflicts)
        #pragma unroll
        for (int i = 0; i < 4; ++i) {
            int b = b0 + i;
            #pragma unroll
            for (int j = 0; j < 8; ++j) {
                float2 f = unpack2(acc[i][j]);
                psum[kw * PS_W + b * 33 + rg * 8 + j] = f.x + f.y;
            }
        }
        __syncthreads();

        // reduce across 4 k-slice warps + gate nonlinearities; 2 (b,col)/thread
        #pragma unroll
        for (int q = 0; q < 2; ++q) {
            int idx = q * NTHR + tid;
            int b = idx >> 3, col = idx & 7;
            float gi = 0.f, gf = 0.f, gg = 0.f, go = 0.f;
            #pragma unroll
            for (int w = 0; w < 4; ++w) {
                const float* pp = psum + w * PS_W + b * 33 + col;
                gi += pp[0]; gf += pp[8]; gg += pp[16]; go += pp[24];
            }
            const float* gx = Gx_s + tok_s[b] * 32 + col;
            gi += gx[0]; gf += gx[8]; gg += gx[16]; go += gx[24];

            float c_old = c_s[idx];
            float cn = fast_sigmoid(gf) * c_old + fast_sigmoid(gi) * fast_tanh(gg);
            float hv = fast_sigmoid(go) * fast_tanh(cn);
            c_s[idx] = cn;
            if ((t == 0) || (t < sl_s[b])) lc_s[idx] = cn;
            hn[b * NH + j0 + col] = hv;
        }
        __threadfence();
        grid_barrier();
    }

    // ---------------- epilogue ----------------
    #pragma unroll
    for (int q = 0; q < 2; ++q) {
        int idx = q * NTHR + tid;
        int b = idx >> 3, col = idx & 7;
        out[b * NH + j0 + col] = lc_s[idx];
    }
}

extern "C" void kernel_launch(void* const* d_in, const int* in_sizes, int n_in,
                              void* d_out, int out_size)
{
    const int*   tokens = (const int*)d_in[0];
    const int*   seqlen = (const int*)d_in[1];
    const float* emb    = (const float*)d_in[2];
    const float* W_ih   = (const float*)d_in[3];
    const float* W_hh   = (const float*)d_in[4];
    const float* b_ih   = (const float*)d_in[5];
    const float* b_hh   = (const float*)d_in[6];
    float*       out    = (float*)d_out;

    cudaFuncSetAttribute(lstm_persistent,
                         cudaFuncAttributeMaxDynamicSharedMemorySize, SMEM_BYTES);
    lstm_persistent<<<NCTA, NTHR, SMEM_BYTES>>>(tokens, seqlen, emb, W_ih, W_hh,
                                                b_ih, b_hh, out);
}